// round 3
// baseline (speedup 1.0000x reference)
#include <cuda_runtime.h>
#include <cstdint>

// Problem constants (fixed by the reference)
#define BB   32
#define CC   128
#define HH   128
#define WW   128
#define OH   64
#define OW   64
// output plane stride (vals / pos_h / pos_w planes), in elements
#define PLANE (CC * OH * OW)   // 524288

__device__ __forceinline__ void win2x2(float a, float b, float c, float d,
                                       int row0, int col0,
                                       float& val, float& ph, float& pw) {
    // first-max argmax over order [a, b, c, d] == flat idx kh*2+kw
    float best = a; int idx = 0;
    if (b > best) { best = b; idx = 1; }
    if (c > best) { best = c; idx = 2; }
    if (d > best) { best = d; idx = 3; }
    int row = row0 + (idx >> 1);
    int col = col0 + (idx & 1);
    val = best;
    ph = (float)row * (1.0f / (float)HH);
    pw = (float)col * (1.0f / (float)WW);
}

__global__ void __launch_bounds__(256)
pap_pool_kernel(const float* __restrict__ x, float* __restrict__ out) {
    // thread -> (bc, oh, ow8): ow8 indexes 8 consecutive output columns
    // total threads = B*C*OH*(OW/8) = 32*128*64*8 = 2,097,152
    unsigned tid = blockIdx.x * blockDim.x + threadIdx.x;

    unsigned ow8 = tid & 7u;           // OW/8 = 8 groups
    unsigned oh  = (tid >> 3) & 63u;   // OH = 64
    unsigned bc  = tid >> 9;           // b*C + c, 0..4095

    // input: rows (2*oh, 2*oh+1), cols [16*ow8, 16*ow8+16)
    // 32-bit element offsets (input = 2^26 elems, output = ~2^25.6 elems)
    unsigned ibase = (bc * (HH * WW)) + (2u * oh) * WW + 16u * ow8;
    const float4* xr0 = reinterpret_cast<const float4*>(x + ibase);
    const float4* xr1 = xr0 + WW / 4;

    // front-batch all 8 loads (MLP=8, long read burst)
    float4 a0 = xr0[0];
    float4 a1 = xr0[1];
    float4 a2 = xr0[2];
    float4 a3 = xr0[3];
    float4 b0 = xr1[0];
    float4 b1 = xr1[1];
    float4 b2 = xr1[2];
    float4 b3 = xr1[3];

    int row0 = 2 * (int)oh;
    int col0 = 16 * (int)ow8;

    float v[8], ph[8], pw[8];
    win2x2(a0.x, a0.y, b0.x, b0.y, row0, col0 +  0, v[0], ph[0], pw[0]);
    win2x2(a0.z, a0.w, b0.z, b0.w, row0, col0 +  2, v[1], ph[1], pw[1]);
    win2x2(a1.x, a1.y, b1.x, b1.y, row0, col0 +  4, v[2], ph[2], pw[2]);
    win2x2(a1.z, a1.w, b1.z, b1.w, row0, col0 +  6, v[3], ph[3], pw[3]);
    win2x2(a2.x, a2.y, b2.x, b2.y, row0, col0 +  8, v[4], ph[4], pw[4]);
    win2x2(a2.z, a2.w, b2.z, b2.w, row0, col0 + 10, v[5], ph[5], pw[5]);
    win2x2(a3.x, a3.y, b3.x, b3.y, row0, col0 + 12, v[6], ph[6], pw[6]);
    win2x2(a3.z, a3.w, b3.z, b3.w, row0, col0 + 14, v[7], ph[7], pw[7]);

    // output: [B, 3C, OH, OW]; b = bc/128, c = bc%128
    unsigned b = bc >> 7;
    unsigned c = bc & 127u;
    float* o = out + ((b * 3u * CC + c) * OH + oh) * OW + 8u * ow8;

    // back-batch all 6 wide stores (long write burst)
    reinterpret_cast<float4*>(o)[0]             = make_float4(v[0],  v[1],  v[2],  v[3]);
    reinterpret_cast<float4*>(o)[1]             = make_float4(v[4],  v[5],  v[6],  v[7]);
    reinterpret_cast<float4*>(o + PLANE)[0]     = make_float4(ph[0], ph[1], ph[2], ph[3]);
    reinterpret_cast<float4*>(o + PLANE)[1]     = make_float4(ph[4], ph[5], ph[6], ph[7]);
    reinterpret_cast<float4*>(o + 2 * PLANE)[0] = make_float4(pw[0], pw[1], pw[2], pw[3]);
    reinterpret_cast<float4*>(o + 2 * PLANE)[1] = make_float4(pw[4], pw[5], pw[6], pw[7]);
}

extern "C" void kernel_launch(void* const* d_in, const int* in_sizes, int n_in,
                              void* d_out, int out_size) {
    const float* x = (const float*)d_in[0];
    float* out = (float*)d_out;
    // 2,097,152 threads total
    const unsigned nthreads = BB * CC * OH * (OW / 8);
    const unsigned block = 256;
    pap_pool_kernel<<<nthreads / block, block>>>(x, out);
}

// round 4
// speedup vs baseline: 1.1388x; 1.1388x over previous
#include <cuda_runtime.h>
#include <cstdint>

// Problem constants (fixed by the reference)
#define BB   32
#define CC   128
#define HH   128
#define WW   128
#define OH   64
#define OW   64
// output plane stride (vals / pos_h / pos_w planes), in elements
#define PLANE (CC * OH * OW)   // 524288

__device__ __forceinline__ void win2x2(float a, float b, float c, float d,
                                       int row0, int col0,
                                       float& val, float& ph, float& pw) {
    // first-max argmax over order [a, b, c, d] == flat idx kh*2+kw
    float best = a; int idx = 0;
    if (b > best) { best = b; idx = 1; }
    if (c > best) { best = c; idx = 2; }
    if (d > best) { best = d; idx = 3; }
    int row = row0 + (idx >> 1);
    int col = col0 + (idx & 1);
    val = best;
    ph = (float)row * (1.0f / (float)HH);
    pw = (float)col * (1.0f / (float)WW);
}

__global__ void __launch_bounds__(256)
pap_pool_kernel(const float* __restrict__ x, float* __restrict__ out) {
    // One WARP owns: one bc, two output rows (oh0, oh0+1) = 4 input rows.
    // Lane l loads float4 at column 4*l of each of the 4 input rows:
    // every LDG.128 is 32 lanes x 16B = 512B fully contiguous.
    // total warps = B*C*(OH/2) = 4096*32 = 131072 -> 4,194,304 threads.
    unsigned tid  = blockIdx.x * blockDim.x + threadIdx.x;
    unsigned lane = tid & 31u;
    unsigned w    = tid >> 5;

    unsigned ohp = w & 31u;    // output-row pair index, 0..31
    unsigned bc  = w >> 5;     // b*C + c, 0..4095

    // input rows 4*ohp .. 4*ohp+3 of channel bc
    const float4* p = reinterpret_cast<const float4*>(
        x + bc * (HH * WW) + (4u * ohp) * WW) + lane;

    // front-batch 4 perfectly-coalesced loads (512B/instr, MLP=4)
    float4 r0 = p[0];
    float4 r1 = p[32];
    float4 r2 = p[64];
    float4 r3 = p[96];

    int row0 = 4 * (int)ohp;
    int col0 = 4 * (int)lane;

    // rows (r0,r1) -> output row oh0 = 2*ohp; rows (r2,r3) -> oh0+1
    float va0, pha0, pwa0, va1, pha1, pwa1;
    float vb0, phb0, pwb0, vb1, phb1, pwb1;
    win2x2(r0.x, r0.y, r1.x, r1.y, row0,     col0,     va0, pha0, pwa0);
    win2x2(r0.z, r0.w, r1.z, r1.w, row0,     col0 + 2, va1, pha1, pwa1);
    win2x2(r2.x, r2.y, r3.x, r3.y, row0 + 2, col0,     vb0, phb0, pwb0);
    win2x2(r2.z, r2.w, r3.z, r3.w, row0 + 2, col0 + 2, vb1, phb1, pwb1);

    // output: [B, 3C, OH, OW]; b = bc/128, c = bc%128
    unsigned b = bc >> 7;
    unsigned c = bc & 127u;
    unsigned oh0 = 2u * ohp;
    float* o = out + ((b * 3u * CC + c) * OH + oh0) * OW + 2u * lane;

    // 6 STG.64, each 32 lanes x 8B = 256B contiguous
    *reinterpret_cast<float2*>(o)                  = make_float2(va0, va1);
    *reinterpret_cast<float2*>(o + OW)             = make_float2(vb0, vb1);
    *reinterpret_cast<float2*>(o + PLANE)          = make_float2(pha0, pha1);
    *reinterpret_cast<float2*>(o + PLANE + OW)     = make_float2(phb0, phb1);
    *reinterpret_cast<float2*>(o + 2 * PLANE)      = make_float2(pwa0, pwa1);
    *reinterpret_cast<float2*>(o + 2 * PLANE + OW) = make_float2(pwb0, pwb1);
}

extern "C" void kernel_launch(void* const* d_in, const int* in_sizes, int n_in,
                              void* d_out, int out_size) {
    const float* x = (const float*)d_in[0];
    float* out = (float*)d_out;
    // 4,194,304 threads total
    const unsigned nthreads = BB * CC * (OH / 2) * 32;
    const unsigned block = 256;
    pap_pool_kernel<<<nthreads / block, block>>>(x, out);
}